// round 13
// baseline (speedup 1.0000x reference)
#include <cuda_runtime.h>
#include <cuda_bf16.h>
#include <cstdint>
#include <stdint.h>
#include <math.h>

#define NB 64
#define NR 36
#define ND 1024
#define NCAP 32
#define NWD 40
#define NS 256
#define NPART 5
#define EPSL 1e-8f
#define BNEPS 1e-5f
#define LNEPS 1e-5f
#define SMOOTHF 9.0f

typedef unsigned long long ull;

// ---------------- scratch ----------------
__device__ float g_h[NB*NR*ND];
__device__ float g_imgave[NB*ND];
__device__ float g_bnmu[NR];
__device__ float g_bnvar[NR];
__device__ float g_g[NB*ND];
__device__ float g_wraw[NB*NR];
__device__ float g_imgglo[NB*ND];
__device__ float g_normglo[NB];
__device__ float g_imgpar[NB*NR*ND];
__device__ float g_capave[NCAP*ND];
__device__ float g_le[NCAP*NWD*ND];
__device__ float g_ge[NCAP*ND];
__device__ float g_capglo[NCAP*ND];
__device__ float g_attnraw[(size_t)NCAP*NWD*NB*NR];
__device__ float g_ctx[(size_t)NCAP*NB*NR*ND];
__device__ float g_ctxinv[NCAP*NB*NR];
__device__ float g_simpar[(size_t)NCAP*NB*NR*NS];
__device__ float g_part[8*64*1024];
__device__ float g_part2[8*64*1024];
__device__ __nv_bfloat16 g_wth[2][NS*ND];
__device__ __nv_bfloat16 g_wtl[2][NS*ND];
__device__ __nv_bfloat16 g_imgh[NB*NR*ND], g_imgl[NB*NR*ND];
__device__ __nv_bfloat16 g_caph[NCAP*NWD*ND], g_capl[NCAP*NWD*ND];
__device__ __nv_bfloat16 g_wbh[2][ND*ND], g_wbl[2][ND*ND];
__device__ __nv_bfloat16 g_attnTh[(size_t)NCAP*NB*NR*64], g_attnTl[(size_t)NCAP*NB*NR*64];
__device__ __nv_bfloat16 g_capTh[(size_t)NCAP*ND*64], g_capTl[(size_t)NCAP*ND*64];

// ---------------- helpers ----------------
__device__ __forceinline__ uint32_t smem_u32(const void* p) {
    uint32_t a;
    asm("{ .reg .u64 t; cvta.to.shared.u64 t, %1; cvt.u32.u64 %0, t; }" : "=r"(a) : "l"(p));
    return a;
}

__device__ __forceinline__ void cp_async16(uint32_t dst, const void* src) {
    asm volatile("cp.async.cg.shared.global [%0], [%1], 16;" :: "r"(dst), "l"(src));
}
#define CP_COMMIT() asm volatile("cp.async.commit_group;")
#define CP_WAIT0()  asm volatile("cp.async.wait_group 0;")
#define CP_WAIT1()  asm volatile("cp.async.wait_group 1;")

__device__ __forceinline__ float blockReduceSum256(float v, float* red) {
    int tid = threadIdx.x;
    red[tid] = v; __syncthreads();
    #pragma unroll
    for (int s = 128; s > 0; s >>= 1) {
        if (tid < s) red[tid] += red[tid + s];
        __syncthreads();
    }
    float r = red[0]; __syncthreads();
    return r;
}

__device__ __forceinline__ float warpReduceSum(float v) {
    v += __shfl_xor_sync(0xffffffffu, v, 16);
    v += __shfl_xor_sync(0xffffffffu, v, 8);
    v += __shfl_xor_sync(0xffffffffu, v, 4);
    v += __shfl_xor_sync(0xffffffffu, v, 2);
    v += __shfl_xor_sync(0xffffffffu, v, 1);
    return v;
}

#define LDSM4(r0, r1, r2, r3, addr) \
    asm volatile("ldmatrix.sync.aligned.m8n8.x4.shared.b16 {%0,%1,%2,%3}, [%4];" \
        : "=r"(r0), "=r"(r1), "=r"(r2), "=r"(r3) : "r"(addr))

#define MMA_BF16(d, a, b) \
    asm volatile("mma.sync.aligned.m16n8k16.row.col.f32.bf16.bf16.f32 " \
        "{%0,%1,%2,%3}, {%4,%5,%6,%7}, {%8,%9}, {%0,%1,%2,%3};" \
        : "+f"((d)[0]), "+f"((d)[1]), "+f"((d)[2]), "+f"((d)[3]) \
        : "r"((a)[0]), "r"((a)[1]), "r"((a)[2]), "r"((a)[3]), "r"((b)[0]), "r"((b)[1]))

// ---------------- split kernels ----------------
__global__ void k_split(const float* __restrict__ X, __nv_bfloat16* __restrict__ H,
                        __nv_bfloat16* __restrict__ L, int total) {
    int idx = blockIdx.x * 256 + threadIdx.x;
    if (idx >= total) return;
    float v = X[idx];
    __nv_bfloat16 h = __float2bfloat16(v);
    H[idx] = h;
    L[idx] = __float2bfloat16(v - __bfloat162float(h));
}

__global__ void k_wsplitT(const float* __restrict__ W, __nv_bfloat16* __restrict__ H,
                          __nv_bfloat16* __restrict__ L, int Ncols, int K) {
    int idx = blockIdx.x * 256 + threadIdx.x;
    if (idx >= Ncols * K) return;
    int n = idx / K, k = idx - n * K;
    float w = W[(size_t)k * Ncols + n];
    __nv_bfloat16 h = __float2bfloat16(w);
    H[idx] = h;
    L[idx] = __float2bfloat16(w - __bfloat162float(h));
}

__global__ void k_capT(const float* __restrict__ cap) {
    int idx = blockIdx.x * 256 + threadIdx.x;
    int k = idx & 63, n = (idx >> 6) & 1023, c = idx >> 16;
    float v = (k < NWD) ? cap[((size_t)c*NWD + k)*ND + n] : 0.f;
    __nv_bfloat16 h = __float2bfloat16(v);
    g_capTh[idx] = h;
    g_capTl[idx] = __float2bfloat16(v - __bfloat162float(h));
}

#define APAD 40
#define GS_STAGE 40960
#define GS_TOTAL (2*GS_STAGE)
#define DS_AH 0
#define DS_AL 10240
#define DS_BH 20480
#define DS_BL 61440
#define DS_RED 102400
#define DS_INV 103424
#define DS_TOTAL 103680

// ============ generic HMMA GEMM, cp.async double-buffered, optional batch ============
template<int ACT>
__global__ void __launch_bounds__(256)
hmma_gemm(const __nv_bfloat16* __restrict__ Ah, const __nv_bfloat16* __restrict__ Al,
          const __nv_bfloat16* __restrict__ Bh, const __nv_bfloat16* __restrict__ Bl,
          const float* __restrict__ bias, float* __restrict__ C, int N, int K,
          size_t strideA, size_t strideB, size_t strideC)
{
    extern __shared__ char smem[];
    uint32_t sb = smem_u32(smem);
    int tid = threadIdx.x, lane = tid & 31, warp = tid >> 5;
    int mw = warp >> 2, nw = warp & 3;
    int n0 = blockIdx.x * 128, m0 = blockIdx.y * 128;
    size_t zA = (size_t)blockIdx.z * strideA;
    size_t zB = (size_t)blockIdx.z * strideB;
    C += (size_t)blockIdx.z * strideC;
    const __nv_bfloat16* Ah0 = Ah + zA + (size_t)m0 * K;
    const __nv_bfloat16* Al0 = Al + zA + (size_t)m0 * K;
    const __nv_bfloat16* Bh0 = Bh + zB + (size_t)n0 * K;
    const __nv_bfloat16* Bl0 = Bl + zB + (size_t)n0 * K;

    float acc[4][4][4];
    #pragma unroll
    for (int i = 0; i < 4; i++)
        #pragma unroll
        for (int j = 0; j < 4; j++)
            #pragma unroll
            for (int e = 0; e < 4; e++) acc[i][j][e] = 0.f;

    int a_row = mw*64 + (lane & 15);
    int a_col8 = (lane >> 4) * 8;
    int b_row = nw*32 + (lane >> 4)*8 + (lane & 7);
    int b_col8 = ((lane >> 3) & 1) * 8;
    const int NCH = K / 32;

    auto issue = [&](int ch, int stage) {
        int k0 = ch * 32;
        uint32_t base = sb + stage * GS_STAGE;
        #pragma unroll
        for (int i = 0; i < 2; i++) {
            int slot = tid + i*256;
            int row = slot >> 2, c = slot & 3;
            uint32_t so = (uint32_t)(row*APAD + c*8) * 2;
            size_t src = (size_t)row*K + k0 + c*8;
            cp_async16(base + 0     + so, Ah0 + src);
            cp_async16(base + 10240 + so, Al0 + src);
            cp_async16(base + 20480 + so, Bh0 + src);
            cp_async16(base + 30720 + so, Bl0 + src);
        }
    };

    issue(0, 0); CP_COMMIT();
    for (int ch = 0; ch < NCH; ch++) {
        int stage = ch & 1;
        if (ch + 1 < NCH) { issue(ch + 1, stage ^ 1); CP_COMMIT(); CP_WAIT1(); }
        else CP_WAIT0();
        __syncthreads();
        uint32_t aA = sb + stage * GS_STAGE;
        uint32_t aAl2 = aA + 10240, aB = aA + 20480, aBl2 = aA + 30720;
        #pragma unroll
        for (int k16 = 0; k16 < 2; k16++) {
            uint32_t bh[4][2], bl[4][2];
            #pragma unroll
            for (int half = 0; half < 2; half++) {
                uint32_t off = (uint32_t)((b_row + half*16)*APAD + k16*16 + b_col8) * 2;
                uint32_t r0, r1, r2, r3;
                LDSM4(r0, r1, r2, r3, aB + off);
                bh[half*2+0][0] = r0; bh[half*2+0][1] = r1;
                bh[half*2+1][0] = r2; bh[half*2+1][1] = r3;
                LDSM4(r0, r1, r2, r3, aBl2 + off);
                bl[half*2+0][0] = r0; bl[half*2+0][1] = r1;
                bl[half*2+1][0] = r2; bl[half*2+1][1] = r3;
            }
            #pragma unroll
            for (int mt = 0; mt < 4; mt++) {
                uint32_t ah[4], al[4];
                uint32_t off = (uint32_t)((a_row + mt*16)*APAD + k16*16 + a_col8) * 2;
                LDSM4(ah[0], ah[1], ah[2], ah[3], aA + off);
                LDSM4(al[0], al[1], al[2], al[3], aAl2 + off);
                #pragma unroll
                for (int nt = 0; nt < 4; nt++) {
                    MMA_BF16(acc[mt][nt], ah, bh[nt]);
                    MMA_BF16(acc[mt][nt], ah, bl[nt]);
                    MMA_BF16(acc[mt][nt], al, bh[nt]);
                }
            }
        }
        __syncthreads();
    }

    #pragma unroll
    for (int mt = 0; mt < 4; mt++) {
        int mA = m0 + mw*64 + mt*16 + (lane >> 2);
        int mB = mA + 8;
        float* dA = C + (size_t)mA * N;
        float* dB = C + (size_t)mB * N;
        #pragma unroll
        for (int nt = 0; nt < 4; nt++) {
            int n = n0 + nw*32 + nt*8 + (lane & 3)*2;
            float b0 = 0.f, b1 = 0.f;
            if (bias) { b0 = bias[n]; b1 = bias[n+1]; }
            float v0 = acc[mt][nt][0] + b0, v1 = acc[mt][nt][1] + b1;
            float v2 = acc[mt][nt][2] + b0, v3 = acc[mt][nt][3] + b1;
            if (ACT == 1) { v0 = tanhf(v0); v1 = tanhf(v1); v2 = tanhf(v2); v3 = tanhf(v3); }
            *(float2*)&dA[n] = make_float2(v0, v1);
            *(float2*)&dB[n] = make_float2(v2, v3);
        }
    }
}

// ============ HMMA diff-square GEMM, full-N tile, pipelined ============
template<int MODE>
__global__ void __launch_bounds__(256)
hmma_diffsq(const float* __restrict__ X, const float* __restrict__ Y,
            const float* __restrict__ rowinv,
            const __nv_bfloat16* __restrict__ Bh, const __nv_bfloat16* __restrict__ Bl,
            const float* __restrict__ bias, float* __restrict__ outp)
{
    extern __shared__ char smem[];
    uint32_t sb = smem_u32(smem);
    float* sred = (float*)(smem + DS_RED);
    float* sinv = (float*)(smem + DS_INV);
    int tid = threadIdx.x;
    int lane = tid & 31, warp = tid >> 5;
    int mw = warp >> 2, nw = warp & 3;
    int m0 = blockIdx.x * 128, z = blockIdx.y;

    const float* Xp = (MODE == 0) ? X + ((size_t)z*2304 + m0)*ND : X + (size_t)m0*ND;
    const float* Yp = (MODE == 0) ? Y + (size_t)m0*ND : Y + (size_t)z*ND;
    const float* invp = (MODE == 0) ? rowinv + (size_t)z*2304 + m0 : nullptr;

    float acc[4][8][4];
    #pragma unroll
    for (int i = 0; i < 4; i++)
        #pragma unroll
        for (int j = 0; j < 8; j++)
            #pragma unroll
            for (int e = 0; e < 4; e++) acc[i][j][e] = 0.f;

    int a_row = mw*64 + (lane & 15);
    int a_col8 = (lane >> 4) * 8;
    int b_row = nw*64 + (lane >> 4)*8 + (lane & 7);
    int b_col8 = ((lane >> 3) & 1) * 8;

    int arow[4], aq[4];
    float ivr[4];
    #pragma unroll
    for (int i = 0; i < 4; i++) {
        int slot = tid + i*256;
        arow[i] = slot >> 3; aq[i] = slot & 7;
        ivr[i] = (MODE == 0) ? invp[arow[i]] : 1.f;
    }

    float4 xr[4], yr[4];
    auto load_regs = [&](int ch) {
        int k0 = ch * 32;
        #pragma unroll
        for (int i = 0; i < 4; i++) {
            size_t off = (size_t)arow[i]*ND + k0 + aq[i]*4;
            xr[i] = *(const float4*)(Xp + off);
            if (MODE == 0) yr[i] = *(const float4*)(Yp + off);
            else           yr[i] = *(const float4*)(Yp + k0 + aq[i]*4);
        }
    };
    auto issueB = [&](int ch, int stage) {
        int k0 = ch * 32;
        uint32_t bh = sb + DS_BH + stage*20480;
        uint32_t bl = sb + DS_BL + stage*20480;
        #pragma unroll
        for (int i = 0; i < 4; i++) {
            int slot = tid + i*256;
            int row = slot >> 2, c = slot & 3;
            uint32_t so = (uint32_t)(row*APAD + c*8) * 2;
            size_t src = (size_t)row*ND + k0 + c*8;
            cp_async16(bh + so, Bh + src);
            cp_async16(bl + so, Bl + src);
        }
    };

    load_regs(0);
    issueB(0, 0); CP_COMMIT();

    for (int ch = 0; ch < 32; ch++) {
        int stage = ch & 1;
        #pragma unroll
        for (int i = 0; i < 4; i++) {
            float iv = ivr[i];
            float d0, d1, d2, d3;
            if (MODE == 0) {
                d0 = xr[i].x*iv - yr[i].x; d1 = xr[i].y*iv - yr[i].y;
                d2 = xr[i].z*iv - yr[i].z; d3 = xr[i].w*iv - yr[i].w;
            } else {
                d0 = xr[i].x - yr[i].x; d1 = xr[i].y - yr[i].y;
                d2 = xr[i].z - yr[i].z; d3 = xr[i].w - yr[i].w;
            }
            float a0 = d0*d0, a1 = d1*d1, a2 = d2*d2, a3 = d3*d3;
            __nv_bfloat162 h01 = __floats2bfloat162_rn(a0, a1);
            __nv_bfloat162 h23 = __floats2bfloat162_rn(a2, a3);
            float r0 = a0 - __bfloat162float(h01.x);
            float r1 = a1 - __bfloat162float(h01.y);
            float r2 = a2 - __bfloat162float(h23.x);
            float r3 = a3 - __bfloat162float(h23.y);
            __nv_bfloat162 l01 = __floats2bfloat162_rn(r0, r1);
            __nv_bfloat162 l23 = __floats2bfloat162_rn(r2, r3);
            uint32_t so = (uint32_t)(arow[i]*APAD + aq[i]*4) * 2;
            *(uint2*)(smem + DS_AH + so) = make_uint2(*(uint32_t*)&h01, *(uint32_t*)&h23);
            *(uint2*)(smem + DS_AL + so) = make_uint2(*(uint32_t*)&l01, *(uint32_t*)&l23);
        }
        if (ch < 31) {
            load_regs(ch + 1);
            issueB(ch + 1, stage ^ 1); CP_COMMIT();
            CP_WAIT1();
        } else {
            CP_WAIT0();
        }
        __syncthreads();
        uint32_t aAh = sb + DS_AH, aAl = sb + DS_AL;
        uint32_t aBh = sb + DS_BH + stage*20480;
        uint32_t aBl = sb + DS_BL + stage*20480;
        #pragma unroll
        for (int k16 = 0; k16 < 2; k16++) {
            uint32_t bh[8][2], bl[8][2];
            #pragma unroll
            for (int p = 0; p < 4; p++) {
                uint32_t off = (uint32_t)((b_row + p*16)*APAD + k16*16 + b_col8) * 2;
                uint32_t r0, r1, r2, r3;
                LDSM4(r0, r1, r2, r3, aBh + off);
                bh[p*2+0][0] = r0; bh[p*2+0][1] = r1;
                bh[p*2+1][0] = r2; bh[p*2+1][1] = r3;
                LDSM4(r0, r1, r2, r3, aBl + off);
                bl[p*2+0][0] = r0; bl[p*2+0][1] = r1;
                bl[p*2+1][0] = r2; bl[p*2+1][1] = r3;
            }
            #pragma unroll
            for (int mt = 0; mt < 4; mt++) {
                uint32_t ah[4], al[4];
                uint32_t off = (uint32_t)((a_row + mt*16)*APAD + k16*16 + a_col8) * 2;
                LDSM4(ah[0], ah[1], ah[2], ah[3], aAh + off);
                LDSM4(al[0], al[1], al[2], al[3], aAl + off);
                #pragma unroll
                for (int nt = 0; nt < 8; nt++) {
                    MMA_BF16(acc[mt][nt], ah, bh[nt]);
                    MMA_BF16(acc[mt][nt], ah, bl[nt]);
                    MMA_BF16(acc[mt][nt], al, bh[nt]);
                }
            }
        }
        __syncthreads();
    }

    #pragma unroll
    for (int mt = 0; mt < 4; mt++) {
        int lmA = mw*64 + mt*16 + (lane >> 2);
        int lmB = lmA + 8;
        int mA = m0 + lmA, mB = m0 + lmB;
        float vA[8][2], vB[8][2];
        float ssqA = 0.f, ssqB = 0.f;
        #pragma unroll
        for (int nt = 0; nt < 8; nt++) {
            int n = nw*64 + nt*8 + (lane & 3)*2;
            float b0 = bias[n], b1 = bias[n+1];
            vA[nt][0] = fmaxf(acc[mt][nt][0] + b0, 0.f);
            vA[nt][1] = fmaxf(acc[mt][nt][1] + b1, 0.f);
            vB[nt][0] = fmaxf(acc[mt][nt][2] + b0, 0.f);
            vB[nt][1] = fmaxf(acc[mt][nt][3] + b1, 0.f);
            if (MODE == 0) {
                ssqA += vA[nt][0]*vA[nt][0] + vA[nt][1]*vA[nt][1];
                ssqB += vB[nt][0]*vB[nt][0] + vB[nt][1]*vB[nt][1];
            }
        }
        float invA = 1.f, invB = 1.f;
        if (MODE == 0) {
            ssqA += __shfl_xor_sync(0xffffffffu, ssqA, 1);
            ssqA += __shfl_xor_sync(0xffffffffu, ssqA, 2);
            ssqB += __shfl_xor_sync(0xffffffffu, ssqB, 1);
            ssqB += __shfl_xor_sync(0xffffffffu, ssqB, 2);
            if ((lane & 3) == 0) {
                sred[nw*64 + mw*32 + (lane >> 2)] = ssqA;
                sred[nw*64 + mw*32 + 16 + (lane >> 2)] = ssqB;
            }
            __syncthreads();
            if (tid < 64) {
                float s = sred[0*64 + tid] + sred[1*64 + tid] + sred[2*64 + tid] + sred[3*64 + tid];
                sinv[tid] = 1.f / (sqrtf(s) + EPSL);
            }
            __syncthreads();
            invA = sinv[mw*32 + (lane >> 2)];
            invB = sinv[mw*32 + 16 + (lane >> 2)];
        }
        float* dA;
        float* dB;
        if (MODE == 0) {
            int bA = mA / NR, rA2 = mA % NR;
            int bB = mB / NR, rB2 = mB % NR;
            dA = outp + (((size_t)z*NB + bA)*37 + 1 + rA2)*NS;
            dB = outp + (((size_t)z*NB + bB)*37 + 1 + rB2)*NS;
        } else {
            dA = outp + ((size_t)z*2304 + mA)*NS;
            dB = outp + ((size_t)z*2304 + mB)*NS;
        }
        #pragma unroll
        for (int nt = 0; nt < 8; nt++) {
            int n = nw*64 + nt*8 + (lane & 3)*2;
            *(float2*)&dA[n] = make_float2(vA[nt][0]*invA, vA[nt][1]*invA);
            *(float2*)&dB[n] = make_float2(vB[nt][0]*invB, vB[nt][1]*invB);
        }
        if (MODE == 0) __syncthreads();
    }
}

// ============ small-M GEMM via split-K ============
__global__ void gemm_small_part(const float* __restrict__ A, const float* __restrict__ W,
                                float* __restrict__ part, int M, int N, int K)
{
    const int BK = 16;
    __shared__ float As[BK][64];
    __shared__ float Bs[BK][64];
    int tid = threadIdx.x, tr = tid >> 4, tc = tid & 15;
    int n0 = blockIdx.x * 64;
    int KS = gridDim.y;
    int Kc = K / KS;
    int kz = blockIdx.y;
    float acc[4][4] = {};
    for (int k0 = kz*Kc; k0 < (kz+1)*Kc; k0 += BK) {
        for (int i = tid; i < 64*BK; i += 256) {
            int m = i >> 4, k = i & 15;
            As[k][m] = (m < M) ? A[(size_t)m*K + k0 + k] : 0.f;
        }
        for (int i = tid; i < BK*64; i += 256) {
            int k = i >> 6, n = i & 63;
            Bs[k][n] = W[(size_t)(k0+k)*N + n0 + n];
        }
        __syncthreads();
        #pragma unroll
        for (int k = 0; k < BK; k++) {
            float a[4], b[4];
            #pragma unroll
            for (int i = 0; i < 4; i++) a[i] = As[k][tr*4+i];
            #pragma unroll
            for (int j = 0; j < 4; j++) b[j] = Bs[k][tc*4+j];
            #pragma unroll
            for (int i = 0; i < 4; i++)
                #pragma unroll
                for (int j = 0; j < 4; j++) acc[i][j] += a[i]*b[j];
        }
        __syncthreads();
    }
    #pragma unroll
    for (int i = 0; i < 4; i++) {
        int m = tr*4 + i;
        if (m >= M) continue;
        #pragma unroll
        for (int j = 0; j < 4; j++)
            part[((size_t)kz*M + m)*N + n0 + tc*4 + j] = acc[i][j];
    }
}

template<int ACT>
__global__ void k_small_epi(const float* __restrict__ part, const float* __restrict__ bias,
                            float* __restrict__ C, int M, int N, int KS)
{
    int idx = blockIdx.x*256 + threadIdx.x;
    if (idx >= M*N) return;
    int n = idx % N;
    float s = 0.f;
    for (int kz = 0; kz < KS; kz++) s += part[(size_t)kz*M*N + idx];
    s += bias[n];
    if (ACT == 1) s = tanhf(s);
    C[idx] = s;
}

// ---------------- tiny glo diff-square GEMM ----------------
__global__ void gemm_diffsq_glo(const float* __restrict__ X, const float* __restrict__ Y,
                                const float* __restrict__ W, const float* __restrict__ bias,
                                float* __restrict__ Cbase, int M, int N, int K)
{
    const int BM = 64, BN = 64, BK = 16;
    int c = blockIdx.z;
    const float* Yp = Y + (size_t)c*K;
    __shared__ float As[BK][BM];
    __shared__ float Bs[BK][BN];
    int tid = threadIdx.x;
    int tr = tid >> 4, tc = tid & 15;
    int m0 = blockIdx.y * BM, n0 = blockIdx.x * BN;
    float acc[4][4] = {};
    for (int k0 = 0; k0 < K; k0 += BK) {
        #pragma unroll
        for (int i = tid; i < BM*BK; i += 256) {
            int m = i >> 4, k = i & 15;
            float v = 0.f;
            if (m0 + m < M) {
                float d = X[(size_t)(m0+m)*K + k0 + k] - Yp[k0 + k];
                v = d * d;
            }
            As[k][m] = v;
        }
        #pragma unroll
        for (int i = tid; i < BK*BN; i += 256) {
            int k = i >> 6, n = i & 63;
            Bs[k][n] = W[(size_t)(k0+k)*N + n0 + n];
        }
        __syncthreads();
        #pragma unroll
        for (int k = 0; k < BK; k++) {
            float a[4], b[4];
            #pragma unroll
            for (int i = 0; i < 4; i++) a[i] = As[k][tr*4+i];
            #pragma unroll
            for (int j = 0; j < 4; j++) b[j] = Bs[k][tc*4+j];
            #pragma unroll
            for (int i = 0; i < 4; i++)
                #pragma unroll
                for (int j = 0; j < 4; j++) acc[i][j] += a[i]*b[j];
        }
        __syncthreads();
    }
    #pragma unroll
    for (int i = 0; i < 4; i++) {
        int m = m0 + tr*4 + i;
        if (m >= M) continue;
        #pragma unroll
        for (int j = 0; j < 4; j++) {
            int n = n0 + tc*4 + j;
            float v = fmaxf(acc[i][j] + bias[n], 0.f);
            Cbase[(size_t)c*M*N + (size_t)m*N + n] = v;
        }
    }
}

// ---------------- small kernels ----------------
__global__ void k_imgave(const float* __restrict__ img) {
    int i = blockIdx.x*blockDim.x + threadIdx.x;
    int b = i >> 10, d = i & 1023;
    float s = 0.f;
    for (int r = 0; r < NR; r++) s += img[((size_t)b*NR + r)*ND + d];
    g_imgave[i] = s * (1.f / NR);
}

__global__ void k_bnstats() {
    int r = blockIdx.x;
    __shared__ float red[256], red2[256];
    float s = 0.f, ss = 0.f;
    for (int i = threadIdx.x; i < NB*ND; i += 256) {
        int b = i >> 10, d = i & 1023;
        float v = g_h[((size_t)b*NR + r)*ND + d];
        s += v; ss += v*v;
    }
    red[threadIdx.x] = s; red2[threadIdx.x] = ss; __syncthreads();
    for (int st = 128; st > 0; st >>= 1) {
        if (threadIdx.x < st) { red[threadIdx.x] += red[threadIdx.x+st]; red2[threadIdx.x] += red2[threadIdx.x+st]; }
        __syncthreads();
    }
    if (threadIdx.x == 0) {
        float mu = red[0] / (float)(NB*ND);
        g_bnmu[r] = mu;
        g_bnvar[r] = red2[0] / (float)(NB*ND) - mu*mu;
    }
}

__global__ void k_gbn(const float* __restrict__ gamma, const float* __restrict__ beta) {
    int d = blockIdx.x*blockDim.x + threadIdx.x;
    float s = 0.f, ss = 0.f;
    for (int b = 0; b < NB; b++) { float v = g_g[(size_t)b*ND + d]; s += v; ss += v*v; }
    float mu = s / NB;
    float var = ss / NB - mu*mu;
    float inv = rsqrtf(var + BNEPS);
    float ga = gamma[d], be = beta[d];
    for (int b = 0; b < NB; b++) {
        float v = g_g[(size_t)b*ND + d];
        g_g[(size_t)b*ND + d] = tanhf((v - mu)*inv*ga + be);
    }
}

__global__ void k_wraw(const float* __restrict__ vcw, const float* __restrict__ vcb,
                       const float* __restrict__ lg, const float* __restrict__ lb) {
    int br = blockIdx.x;
    int b = br / NR, r = br % NR;
    __shared__ float red[256];
    float mu = g_bnmu[r], inv = rsqrtf(g_bnvar[r] + BNEPS);
    float ga = lg[r], be = lb[r];
    float s = 0.f;
    for (int d = threadIdx.x; d < ND; d += 256) {
        float le = tanhf((g_h[(size_t)br*ND + d] - mu)*inv*ga + be);
        s += le * g_g[(size_t)b*ND + d] * vcw[d];
    }
    float tot = blockReduceSum256(s, red);
    if (threadIdx.x == 0) g_wraw[br] = tot + vcb[0];
}

__global__ void k_newglobal(const float* __restrict__ img) {
    int b = blockIdx.x;
    __shared__ float w[NR];
    __shared__ float red[256];
    __shared__ float invn;
    if (threadIdx.x == 0) {
        float mx = -1e30f;
        for (int r = 0; r < NR; r++) mx = fmaxf(mx, g_wraw[b*NR + r]);
        float sum = 0.f;
        for (int r = 0; r < NR; r++) { w[r] = expf(g_wraw[b*NR + r] - mx); sum += w[r]; }
        float is = 1.f / sum;
        for (int r = 0; r < NR; r++) w[r] *= is;
    }
    __syncthreads();
    float ssq = 0.f;
    for (int d = threadIdx.x; d < ND; d += 256) {
        float s = 0.f;
        for (int r = 0; r < NR; r++) s += w[r] * img[((size_t)b*NR + r)*ND + d];
        g_imgglo[(size_t)b*ND + d] = s;
        ssq += s*s;
    }
    float tot = blockReduceSum256(ssq, red);
    if (threadIdx.x == 0) {
        float nrm = sqrtf(tot) + EPSL;
        g_normglo[b] = nrm;
        invn = 1.f / nrm;
    }
    __syncthreads();
    for (int d = threadIdx.x; d < ND; d += 256) g_imgglo[(size_t)b*ND + d] *= invn;
}

__global__ void k_imgpar(const float* __restrict__ img, const int* __restrict__ adjs) {
    int br = blockIdx.x;
    int b = br / NR, r = br % NR;
    __shared__ int eff[NPART];
    __shared__ float wg[NPART];
    if (threadIdx.x == 0) {
        int cnt = 0;
        const int* row = adjs + (size_t)b*NR*NR + (size_t)r*NR;
        for (int j = 0; j < NR && cnt < NPART; j++)
            if (row[j] == 1) eff[cnt++] = j;
        for (; cnt < NPART; cnt++) eff[cnt] = r;
        float v[NPART], mx = -1e30f;
        for (int k = 0; k < NPART; k++) { v[k] = g_wraw[b*NR + eff[k]]; mx = fmaxf(mx, v[k]); }
        float sum = 0.f;
        for (int k = 0; k < NPART; k++) { v[k] = expf(v[k] - mx); sum += v[k]; }
        float is = 1.f / sum;
        for (int k = 0; k < NPART; k++) wg[k] = v[k]*is;
    }
    __syncthreads();
    float invn = 1.f / g_normglo[b];
    for (int d = threadIdx.x; d < ND; d += 256) {
        float s = 0.f;
        #pragma unroll
        for (int k = 0; k < NPART; k++) s += wg[k] * img[((size_t)b*NR + eff[k])*ND + d];
        g_imgpar[(size_t)br*ND + d] = s * invn;
    }
}

__global__ void k_capave(const float* __restrict__ cap) {
    int i = blockIdx.x*blockDim.x + threadIdx.x;
    int c = i >> 10, d = i & 1023;
    float s = 0.f;
    for (int n = 0; n < NWD; n++) s += cap[((size_t)c*NWD + n)*ND + d];
    g_capave[i] = s * (1.f / NWD);
}

__global__ void k_capglo(const float* __restrict__ cap, const float* __restrict__ tsacw,
                         const float* __restrict__ tsacb) {
    int c = blockIdx.x;
    __shared__ float red[256];
    __shared__ float cw[NWD];
    __shared__ float invn;
    float gw[4];
    #pragma unroll
    for (int i = 0; i < 4; i++) {
        int d = threadIdx.x + i*256;
        gw[i] = g_ge[(size_t)c*ND + d] * tsacw[d];
    }
    for (int n = 0; n < NWD; n++) {
        float s = 0.f;
        #pragma unroll
        for (int i = 0; i < 4; i++) {
            int d = threadIdx.x + i*256;
            s += g_le[((size_t)c*NWD + n)*ND + d] * gw[i];
        }
        float tot = blockReduceSum256(s, red);
        if (threadIdx.x == 0) cw[n] = tot + tsacb[0];
    }
    __syncthreads();
    if (threadIdx.x == 0) {
        float mx = -1e30f;
        for (int n = 0; n < NWD; n++) mx = fmaxf(mx, cw[n]);
        float sum = 0.f;
        for (int n = 0; n < NWD; n++) { cw[n] = expf(cw[n] - mx); sum += cw[n]; }
        float is = 1.f / sum;
        for (int n = 0; n < NWD; n++) cw[n] *= is;
    }
    __syncthreads();
    float ssq = 0.f;
    #pragma unroll
    for (int i = 0; i < 4; i++) {
        int d = threadIdx.x + i*256;
        float s = 0.f;
        for (int n = 0; n < NWD; n++) s += cw[n] * cap[((size_t)c*NWD + n)*ND + d];
        g_capglo[(size_t)c*ND + d] = s;
        ssq += s*s;
    }
    float tot = blockReduceSum256(ssq, red);
    if (threadIdx.x == 0) invn = 1.f / (sqrtf(tot) + EPSL);
    __syncthreads();
    #pragma unroll
    for (int i = 0; i < 4; i++) {
        int d = threadIdx.x + i*256;
        g_capglo[(size_t)c*ND + d] *= invn;
    }
}

__global__ void k_attnfuse() {
    int cb = blockIdx.x;
    int c = cb / NB, b = cb % NB;
    __shared__ float sA[NWD*NR];
    __shared__ float nrm[NWD];
    const float* raw = g_attnraw + (size_t)c*NWD*NB*NR;
    for (int i = threadIdx.x; i < NWD*NR; i += 256) {
        int n = i / NR, r = i % NR;
        float v = raw[(size_t)n*NB*NR + (size_t)b*NR + r];
        v = (v > 0.f) ? v : 0.1f*v;
        sA[i] = v;
    }
    __syncthreads();
    if (threadIdx.x < NWD) {
        int n = threadIdx.x;
        float s = 0.f;
        for (int r = 0; r < NR; r++) { float v = sA[n*NR + r]; s += v*v; }
        nrm[n] = 1.f / (sqrtf(s) + EPSL);
    }
    __syncthreads();
    if (threadIdx.x < NR) {
        int r = threadIdx.x;
        float vals[NWD];
        float mx = -1e30f;
        for (int n = 0; n < NWD; n++) {
            float v = SMOOTHF * sA[n*NR + r] * nrm[n];
            vals[n] = v;
            mx = fmaxf(mx, v);
        }
        float sum = 0.f;
        for (int n = 0; n < NWD; n++) { vals[n] = expf(vals[n] - mx); sum += vals[n]; }
        float is = 1.f / sum;
        size_t base = ((size_t)cb*NR + r) * 64;
        for (int n = 0; n < 64; n++) {
            float w = (n < NWD) ? vals[n]*is : 0.f;
            __nv_bfloat16 h = __float2bfloat16(w);
            g_attnTh[base + n] = h;
            g_attnTl[base + n] = __float2bfloat16(w - __bfloat162float(h));
        }
    }
}

__global__ void k_ctxssq() {
    int row = blockIdx.x * 8 + (threadIdx.x >> 5);
    int lane = threadIdx.x & 31;
    const float* p = g_ctx + (size_t)row * ND;
    float s = 0.f;
    #pragma unroll
    for (int i = 0; i < 8; i++) {
        float4 v = *(const float4*)(p + lane*4 + i*128);
        s += v.x*v.x + v.y*v.y + v.z*v.z + v.w*v.w;
    }
    s = warpReduceSum(s);
    if (lane == 0) g_ctxinv[row] = 1.f / (sqrtf(s) + EPSL);
}

__global__ void k_rownorm(float* __restrict__ X, int L) {
    size_t row = blockIdx.x;
    float* p = X + row*(size_t)L;
    __shared__ float red[256];
    __shared__ float invn;
    float s = 0.f;
    for (int i = threadIdx.x; i < L; i += 256) { float v = p[i]; s += v*v; }
    float tot = blockReduceSum256(s, red);
    if (threadIdx.x == 0) invn = 1.f / (sqrtf(tot) + EPSL);
    __syncthreads();
    for (int i = threadIdx.x; i < L; i += 256) p[i] *= invn;
}

__global__ void k_finalize(const float* __restrict__ simw, const float* __restrict__ simb,
                           const float* __restrict__ lng, const float* __restrict__ lnb,
                           float* __restrict__ out, size_t out2off) {
    int cb = blockIdx.x;
    int tid = threadIdx.x;
    int lane = tid & 31, warp = tid >> 5;
    const float* sg = out + out2off + (size_t)cb*NS;
    __shared__ float sSgw[NS];
    __shared__ float wv[NR];
    __shared__ float mv[2];
    float sgv = sg[tid];
    sSgw[tid] = sgv * simw[tid];
    __syncthreads();
    const float* sp = g_simpar + (size_t)cb*NR*NS;
    for (int r = warp; r < NR; r += 8) {
        const float* row = sp + (size_t)r*NS;
        float dot = 0.f, ss = 0.f;
        #pragma unroll
        for (int i = 0; i < 8; i++) {
            int c = lane + i*32;
            float v = row[c];
            dot += v * sSgw[c];
            ss += v * v;
        }
        dot = warpReduceSum(dot);
        ss = warpReduceSum(ss);
        if (lane == 0) wv[r] = dot / (sqrtf(ss) + EPSL) + simb[0];
    }
    __syncthreads();
    if (tid == 0) {
        float m = 0.f;
        for (int r = 0; r < NR; r++) m += wv[r];
        m /= NR;
        float v = 0.f;
        for (int r = 0; r < NR; r++) { float d = wv[r] - m; v += d*d; }
        v /= NR;
        mv[0] = m; mv[1] = rsqrtf(v + LNEPS);
    }
    __syncthreads();
    if (tid < NR) {
        int r = tid;
        float z = (wv[r] - mv[0])*mv[1]*lng[r] + lnb[r];
        wv[r] = 1.f / (1.f + expf(-z));
    }
    __syncthreads();
    float* ob = out + (size_t)cb*37*NS;
    ob[tid] = sgv;
    for (int r = 0; r < NR; r++) ob[(size_t)(1+r)*NS + tid] *= wv[r];
}

// ---------------- host ----------------
extern "C" void kernel_launch(void* const* d_in, const int* in_sizes, int n_in,
                              void* d_out, int out_size) {
    (void)in_sizes; (void)n_in; (void)out_size;
    const float* img    = (const float*)d_in[0];
    const float* cap    = (const float*)d_in[1];
    const int*   adjs   = (const int*)d_in[3];
    const float* tsa_lw = (const float*)d_in[5];
    const float* tsa_lb = (const float*)d_in[6];
    const float* tsa_gw = (const float*)d_in[7];
    const float* tsa_gb = (const float*)d_in[8];
    const float* tsa_cw = (const float*)d_in[9];
    const float* tsa_cb = (const float*)d_in[10];
    const float* vl_w   = (const float*)d_in[11];
    const float* vl_b   = (const float*)d_in[12];
    const float* vbn_lg = (const float*)d_in[13];
    const float* vbn_lb = (const float*)d_in[14];
    const float* vg_w   = (const float*)d_in[15];
    const float* vg_b   = (const float*)d_in[16];
    const float* vbn_gg = (const float*)d_in[17];
    const float* vbn_gb = (const float*)d_in[18];
    const float* vc_w   = (const float*)d_in[19];
    const float* vc_b   = (const float*)d_in[20];
    const float* loc_w  = (const float*)d_in[21];
    const float* loc_b  = (const float*)d_in[22];
    const float* par_w  = (const float*)d_in[23];
    const float* par_b  = (const float*)d_in[24];
    const float* glo_w  = (const float*)d_in[25];
    const float* glo_b  = (const float*)d_in[26];
    const float* sim_w  = (const float*)d_in[27];
    const float* sim_b  = (const float*)d_in[28];
    const float* ln_g   = (const float*)d_in[29];
    const float* ln_b   = (const float*)d_in[30];
    float* out = (float*)d_out;

    static bool inited = false;
    static float *p_h, *p_imgave, *p_g, *p_ge, *p_le, *p_attnraw,
                 *p_ctx, *p_ctxinv, *p_imgpar, *p_imgglo, *p_capglo, *p_simpar,
                 *p_part, *p_part2, *p_capave;
    static __nv_bfloat16 *p_wth, *p_wtl, *p_imgh, *p_imgl, *p_caph, *p_capl, *p_wbh, *p_wbl,
                         *p_attnTh, *p_attnTl, *p_capTh, *p_capTl;
    static cudaStream_t s1, s2;
    static cudaEvent_t evRoot, evImg, evCap, evImgpar, evD0, evD1;
    if (!inited) {
        cudaGetSymbolAddress((void**)&p_h, g_h);
        cudaGetSymbolAddress((void**)&p_imgave, g_imgave);
        cudaGetSymbolAddress((void**)&p_g, g_g);
        cudaGetSymbolAddress((void**)&p_ge, g_ge);
        cudaGetSymbolAddress((void**)&p_le, g_le);
        cudaGetSymbolAddress((void**)&p_attnraw, g_attnraw);
        cudaGetSymbolAddress((void**)&p_ctx, g_ctx);
        cudaGetSymbolAddress((void**)&p_ctxinv, g_ctxinv);
        cudaGetSymbolAddress((void**)&p_imgpar, g_imgpar);
        cudaGetSymbolAddress((void**)&p_imgglo, g_imgglo);
        cudaGetSymbolAddress((void**)&p_capglo, g_capglo);
        cudaGetSymbolAddress((void**)&p_simpar, g_simpar);
        cudaGetSymbolAddress((void**)&p_part, g_part);
        cudaGetSymbolAddress((void**)&p_part2, g_part2);
        cudaGetSymbolAddress((void**)&p_capave, g_capave);
        cudaGetSymbolAddress((void**)&p_wth, g_wth);
        cudaGetSymbolAddress((void**)&p_wtl, g_wtl);
        cudaGetSymbolAddress((void**)&p_imgh, g_imgh);
        cudaGetSymbolAddress((void**)&p_imgl, g_imgl);
        cudaGetSymbolAddress((void**)&p_caph, g_caph);
        cudaGetSymbolAddress((void**)&p_capl, g_capl);
        cudaGetSymbolAddress((void**)&p_wbh, g_wbh);
        cudaGetSymbolAddress((void**)&p_wbl, g_wbl);
        cudaGetSymbolAddress((void**)&p_attnTh, g_attnTh);
        cudaGetSymbolAddress((void**)&p_attnTl, g_attnTl);
        cudaGetSymbolAddress((void**)&p_capTh, g_capTh);
        cudaGetSymbolAddress((void**)&p_capTl, g_capTl);
        cudaFuncSetAttribute(hmma_gemm<0>, cudaFuncAttributeMaxDynamicSharedMemorySize, GS_TOTAL);
        cudaFuncSetAttribute(hmma_gemm<1>, cudaFuncAttributeMaxDynamicSharedMemorySize, GS_TOTAL);
        cudaFuncSetAttribute(hmma_diffsq<0>, cudaFuncAttributeMaxDynamicSharedMemorySize, DS_TOTAL);
        cudaFuncSetAttribute(hmma_diffsq<1>, cudaFuncAttributeMaxDynamicSharedMemorySize, DS_TOTAL);
        cudaStreamCreateWithFlags(&s1, cudaStreamNonBlocking);
        cudaStreamCreateWithFlags(&s2, cudaStreamNonBlocking);
        cudaEventCreateWithFlags(&evRoot, cudaEventDisableTiming);
        cudaEventCreateWithFlags(&evImg, cudaEventDisableTiming);
        cudaEventCreateWithFlags(&evCap, cudaEventDisableTiming);
        cudaEventCreateWithFlags(&evImgpar, cudaEventDisableTiming);
        cudaEventCreateWithFlags(&evD0, cudaEventDisableTiming);
        cudaEventCreateWithFlags(&evD1, cudaEventDisableTiming);
        inited = true;
    }

    const size_t out2off = (size_t)NCAP*NB*37*NS;
    float* out2 = out + out2off;

    // ================= s0: root + img chain =================
    cudaEventRecord(evRoot, 0);
    k_split<<<(NB*NR*ND+255)/256, 256>>>(img, p_imgh, p_imgl, NB*NR*ND);
    cudaEventRecord(evImg, 0);
    k_wsplitT<<<(ND*ND+255)/256, 256>>>(vl_w, p_wbh, p_wbl, ND, ND);
    k_imgave<<<256, 256>>>(img);
    hmma_gemm<0><<<dim3(8, 18), 256, GS_TOTAL>>>(p_imgh, p_imgl, p_wbh, p_wbl,
                                                 vl_b, p_h, ND, ND, 0, 0, 0);
    k_bnstats<<<NR, 256>>>();
    gemm_small_part<<<dim3(16, 8), 256>>>(p_imgave, vg_w, p_part, NB, ND, ND);
    k_small_epi<0><<<(NB*ND+255)/256, 256>>>(p_part, vg_b, p_g, NB, ND, 8);
    k_gbn<<<4, 256>>>(vbn_gg, vbn_gb);
    k_wraw<<<NB*NR, 256>>>(vc_w, vc_b, vbn_lg, vbn_lb);
    k_newglobal<<<NB, 256>>>(img);
    k_imgpar<<<NB*NR, 256>>>(img, adjs);
    cudaEventRecord(evImgpar, 0);

    // ================= s1: cap chain + diffsq1 branch =================
    cudaStreamWaitEvent(s1, evRoot, 0);
    k_split<<<(NCAP*NWD*ND+255)/256, 256, 0, s1>>>(cap, p_caph, p_capl, NCAP*NWD*ND);
    cudaEventRecord(evCap, s1);
    k_wsplitT<<<(ND*ND+255)/256, 256, 0, s1>>>(tsa_lw, p_wbh + ND*ND, p_wbl + ND*ND, ND, ND);
    k_wsplitT<<<(NS*ND+255)/256, 256, 0, s1>>>(par_w, p_wth + NS*ND, p_wtl + NS*ND, NS, ND);
    hmma_gemm<1><<<dim3(8, 10), 256, GS_TOTAL, s1>>>(p_caph, p_capl, p_wbh + ND*ND, p_wbl + ND*ND,
                                                     tsa_lb, p_le, ND, ND, 0, 0, 0);
    k_capave<<<128, 256, 0, s1>>>(cap);
    gemm_small_part<<<dim3(16, 8), 256, 0, s1>>>(p_capave, tsa_gw, p_part2, NCAP, ND, ND);
    k_small_epi<1><<<(NCAP*ND+255)/256, 256, 0, s1>>>(p_part2, tsa_gb, p_ge, NCAP, ND, 8);
    k_capglo<<<NCAP, 256, 0, s1>>>(cap, tsa_cw, tsa_cb);
    cudaStreamWaitEvent(s1, evImgpar, 0);
    hmma_diffsq<1><<<dim3(18, NCAP), 256, DS_TOTAL, s1>>>(p_imgpar, p_capglo, nullptr,
                                                          p_wth + NS*ND, p_wtl + NS*ND, par_b, p_simpar);
    gemm_diffsq_glo<<<dim3(4, 1, NCAP), 256, 0, s1>>>(p_imgglo, p_capglo, glo_w, glo_b, out2, NB, NS, ND);
    k_rownorm<<<NCAP*NB, 256, 0, s1>>>(out2, NS);
    cudaEventRecord(evD1, s1);

    // ================= s2: attn chain + diffsq0 =================
    cudaStreamWaitEvent(s2, evImg, 0);
    cudaStreamWaitEvent(s2, evCap, 0);
    k_wsplitT<<<(NS*ND+255)/256, 256, 0, s2>>>(loc_w, p_wth, p_wtl, NS, ND);
    k_capT<<<(NCAP*ND*64+255)/256, 256, 0, s2>>>(cap);
    hmma_gemm<0><<<dim3(18, 10), 256, GS_TOTAL, s2>>>(p_caph, p_capl, p_imgh, p_imgl,
                                                      nullptr, p_attnraw, NB*NR, ND, 0, 0, 0);
    k_attnfuse<<<NCAP*NB, 256, 0, s2>>>();
    hmma_gemm<0><<<dim3(8, 18, NCAP), 256, GS_TOTAL, s2>>>(p_attnTh, p_attnTl, p_capTh, p_capTl,
                                                           nullptr, p_ctx, ND, 64,
                                                           (size_t)2304*64, (size_t)ND*64, (size_t)2304*ND);
    k_ctxssq<<<NCAP*NB*NR/8, 256, 0, s2>>>();
    hmma_diffsq<0><<<dim3(18, NCAP), 256, DS_TOTAL, s2>>>(p_ctx, img, p_ctxinv, p_wth, p_wtl, loc_b, out);
    cudaEventRecord(evD0, s2);

    // ================= join + finalize on s0 =================
    cudaStreamWaitEvent(0, evD0, 0);
    cudaStreamWaitEvent(0, evD1, 0);
    k_finalize<<<NCAP*NB, 256>>>(sim_w, sim_b, ln_g, ln_b, out, out2off);
}

// round 17
// speedup vs baseline: 1.0054x; 1.0054x over previous
#include <cuda_runtime.h>
#include <cuda_bf16.h>
#include <cstdint>
#include <stdint.h>
#include <math.h>

#define NB 64
#define NR 36
#define ND 1024
#define NCAP 32
#define NWD 40
#define NS 256
#define NPART 5
#define EPSL 1e-8f
#define BNEPS 1e-5f
#define LNEPS 1e-5f
#define SMOOTHF 9.0f

typedef unsigned long long ull;

// ---------------- scratch ----------------
__device__ float g_h[NB*NR*ND];
__device__ float g_imgave[NB*ND];
__device__ float g_bnmu[NR];
__device__ float g_bnvar[NR];
__device__ float g_g[NB*ND];
__device__ float g_wraw[NB*NR];
__device__ float g_imgglo[NB*ND];
__device__ float g_normglo[NB];
__device__ float g_imgpar[NB*NR*ND];
__device__ float g_capave[NCAP*ND];
__device__ float g_le[NCAP*NWD*ND];
__device__ float g_ge[NCAP*ND];
__device__ float g_capglo[NCAP*ND];
__device__ float g_attnraw[(size_t)NCAP*NWD*NB*NR];
__device__ float g_ctx[(size_t)NCAP*NB*NR*ND];
__device__ float g_ctxinv[NCAP*NB*NR];
__device__ float g_simpar[(size_t)NCAP*NB*NR*NS];
__device__ float g_part[8*64*1024];
__device__ __nv_bfloat16 g_wth[2][NS*ND];
__device__ __nv_bfloat16 g_wtl[2][NS*ND];
__device__ __nv_bfloat16 g_imgh[NB*NR*ND], g_imgl[NB*NR*ND];
__device__ __nv_bfloat16 g_caph[NCAP*NWD*ND], g_capl[NCAP*NWD*ND];
__device__ __nv_bfloat16 g_wbh[2][ND*ND], g_wbl[2][ND*ND];
__device__ __nv_bfloat16 g_attnTh[(size_t)NCAP*NB*NR*64], g_attnTl[(size_t)NCAP*NB*NR*64];
__device__ __nv_bfloat16 g_capTh[(size_t)NCAP*ND*64], g_capTl[(size_t)NCAP*ND*64];

// ---------------- helpers ----------------
__device__ __forceinline__ uint32_t smem_u32(const void* p) {
    uint32_t a;
    asm("{ .reg .u64 t; cvta.to.shared.u64 t, %1; cvt.u32.u64 %0, t; }" : "=r"(a) : "l"(p));
    return a;
}

__device__ __forceinline__ void cp_async16(uint32_t dst, const void* src) {
    asm volatile("cp.async.cg.shared.global [%0], [%1], 16;" :: "r"(dst), "l"(src));
}
#define CP_COMMIT() asm volatile("cp.async.commit_group;")
#define CP_WAIT0()  asm volatile("cp.async.wait_group 0;")
#define CP_WAIT1()  asm volatile("cp.async.wait_group 1;")

__device__ __forceinline__ float blockReduceSum256(float v, float* red) {
    int tid = threadIdx.x;
    red[tid] = v; __syncthreads();
    #pragma unroll
    for (int s = 128; s > 0; s >>= 1) {
        if (tid < s) red[tid] += red[tid + s];
        __syncthreads();
    }
    float r = red[0]; __syncthreads();
    return r;
}

__device__ __forceinline__ float warpReduceSum(float v) {
    v += __shfl_xor_sync(0xffffffffu, v, 16);
    v += __shfl_xor_sync(0xffffffffu, v, 8);
    v += __shfl_xor_sync(0xffffffffu, v, 4);
    v += __shfl_xor_sync(0xffffffffu, v, 2);
    v += __shfl_xor_sync(0xffffffffu, v, 1);
    return v;
}

#define LDSM4(r0, r1, r2, r3, addr) \
    asm volatile("ldmatrix.sync.aligned.m8n8.x4.shared.b16 {%0,%1,%2,%3}, [%4];" \
        : "=r"(r0), "=r"(r1), "=r"(r2), "=r"(r3) : "r"(addr))

#define MMA_BF16(d, a, b) \
    asm volatile("mma.sync.aligned.m16n8k16.row.col.f32.bf16.bf16.f32 " \
        "{%0,%1,%2,%3}, {%4,%5,%6,%7}, {%8,%9}, {%0,%1,%2,%3};" \
        : "+f"((d)[0]), "+f"((d)[1]), "+f"((d)[2]), "+f"((d)[3]) \
        : "r"((a)[0]), "r"((a)[1]), "r"((a)[2]), "r"((a)[3]), "r"((b)[0]), "r"((b)[1]))

// ---------------- split kernels ----------------
__global__ void k_split(const float* __restrict__ X, __nv_bfloat16* __restrict__ H,
                        __nv_bfloat16* __restrict__ L, int total) {
    int idx = blockIdx.x * 256 + threadIdx.x;
    if (idx >= total) return;
    float v = X[idx];
    __nv_bfloat16 h = __float2bfloat16(v);
    H[idx] = h;
    L[idx] = __float2bfloat16(v - __bfloat162float(h));
}

__global__ void k_wsplitT(const float* __restrict__ W, __nv_bfloat16* __restrict__ H,
                          __nv_bfloat16* __restrict__ L, int Ncols, int K) {
    int idx = blockIdx.x * 256 + threadIdx.x;
    if (idx >= Ncols * K) return;
    int n = idx / K, k = idx - n * K;
    float w = W[(size_t)k * Ncols + n];
    __nv_bfloat16 h = __float2bfloat16(w);
    H[idx] = h;
    L[idx] = __float2bfloat16(w - __bfloat162float(h));
}

__global__ void k_capT(const float* __restrict__ cap) {
    int idx = blockIdx.x * 256 + threadIdx.x;
    int k = idx & 63, n = (idx >> 6) & 1023, c = idx >> 16;
    float v = (k < NWD) ? cap[((size_t)c*NWD + k)*ND + n] : 0.f;
    __nv_bfloat16 h = __float2bfloat16(v);
    g_capTh[idx] = h;
    g_capTl[idx] = __float2bfloat16(v - __bfloat162float(h));
}

#define APAD 40
#define GS_STAGE 40960
#define GS_TOTAL (2*GS_STAGE)
#define DS_AH 0
#define DS_AL 10240
#define DS_BH 20480
#define DS_BL 61440
#define DS_RED 102400
#define DS_INV 103424
#define DS_TOTAL 103680

// ============ generic HMMA GEMM, cp.async double-buffered, 2 CTAs/SM ============
template<int ACT>
__global__ void __launch_bounds__(256, 2)
hmma_gemm(const __nv_bfloat16* __restrict__ Ah, const __nv_bfloat16* __restrict__ Al,
          const __nv_bfloat16* __restrict__ Bh, const __nv_bfloat16* __restrict__ Bl,
          const float* __restrict__ bias, float* __restrict__ C, int N, int K,
          size_t strideA, size_t strideB, size_t strideC)
{
    extern __shared__ char smem[];
    uint32_t sb = smem_u32(smem);
    int tid = threadIdx.x, lane = tid & 31, warp = tid >> 5;
    int mw = warp >> 2, nw = warp & 3;
    int n0 = blockIdx.x * 128, m0 = blockIdx.y * 128;
    size_t zA = (size_t)blockIdx.z * strideA;
    size_t zB = (size_t)blockIdx.z * strideB;
    C += (size_t)blockIdx.z * strideC;
    const __nv_bfloat16* Ah0 = Ah + zA + (size_t)m0 * K;
    const __nv_bfloat16* Al0 = Al + zA + (size_t)m0 * K;
    const __nv_bfloat16* Bh0 = Bh + zB + (size_t)n0 * K;
    const __nv_bfloat16* Bl0 = Bl + zB + (size_t)n0 * K;

    float acc[4][4][4];
    #pragma unroll
    for (int i = 0; i < 4; i++)
        #pragma unroll
        for (int j = 0; j < 4; j++)
            #pragma unroll
            for (int e = 0; e < 4; e++) acc[i][j][e] = 0.f;

    int a_row = mw*64 + (lane & 15);
    int a_col8 = (lane >> 4) * 8;
    int b_row = nw*32 + (lane >> 4)*8 + (lane & 7);
    int b_col8 = ((lane >> 3) & 1) * 8;
    const int NCH = K / 32;

    auto issue = [&](int ch, int stage) {
        int k0 = ch * 32;
        uint32_t base = sb + stage * GS_STAGE;
        #pragma unroll
        for (int i = 0; i < 2; i++) {
            int slot = tid + i*256;
            int row = slot >> 2, c = slot & 3;
            uint32_t so = (uint32_t)(row*APAD + c*8) * 2;
            size_t src = (size_t)row*K + k0 + c*8;
            cp_async16(base + 0     + so, Ah0 + src);
            cp_async16(base + 10240 + so, Al0 + src);
            cp_async16(base + 20480 + so, Bh0 + src);
            cp_async16(base + 30720 + so, Bl0 + src);
        }
    };

    issue(0, 0); CP_COMMIT();
    for (int ch = 0; ch < NCH; ch++) {
        int stage = ch & 1;
        if (ch + 1 < NCH) { issue(ch + 1, stage ^ 1); CP_COMMIT(); CP_WAIT1(); }
        else CP_WAIT0();
        __syncthreads();
        uint32_t aA = sb + stage * GS_STAGE;
        uint32_t aAl2 = aA + 10240, aB = aA + 20480, aBl2 = aA + 30720;
        #pragma unroll
        for (int k16 = 0; k16 < 2; k16++) {
            uint32_t bh[4][2], bl[4][2];
            #pragma unroll
            for (int half = 0; half < 2; half++) {
                uint32_t off = (uint32_t)((b_row + half*16)*APAD + k16*16 + b_col8) * 2;
                uint32_t r0, r1, r2, r3;
                LDSM4(r0, r1, r2, r3, aB + off);
                bh[half*2+0][0] = r0; bh[half*2+0][1] = r1;
                bh[half*2+1][0] = r2; bh[half*2+1][1] = r3;
                LDSM4(r0, r1, r2, r3, aBl2 + off);
                bl[half*2+0][0] = r0; bl[half*2+0][1] = r1;
                bl[half*2+1][0] = r2; bl[half*2+1][1] = r3;
            }
            #pragma unroll
            for (int mt = 0; mt < 4; mt++) {
                uint32_t ah[4], al[4];
                uint32_t off = (uint32_t)((a_row + mt*16)*APAD + k16*16 + a_col8) * 2;
                LDSM4(ah[0], ah[1], ah[2], ah[3], aA + off);
                LDSM4(al[0], al[1], al[2], al[3], aAl2 + off);
                #pragma unroll
                for (int nt = 0; nt < 4; nt++) {
                    MMA_BF16(acc[mt][nt], ah, bh[nt]);
                    MMA_BF16(acc[mt][nt], ah, bl[nt]);
                    MMA_BF16(acc[mt][nt], al, bh[nt]);
                }
            }
        }
        __syncthreads();
    }

    #pragma unroll
    for (int mt = 0; mt < 4; mt++) {
        int mA = m0 + mw*64 + mt*16 + (lane >> 2);
        int mB = mA + 8;
        float* dA = C + (size_t)mA * N;
        float* dB = C + (size_t)mB * N;
        #pragma unroll
        for (int nt = 0; nt < 4; nt++) {
            int n = n0 + nw*32 + nt*8 + (lane & 3)*2;
            float b0 = 0.f, b1 = 0.f;
            if (bias) { b0 = bias[n]; b1 = bias[n+1]; }
            float v0 = acc[mt][nt][0] + b0, v1 = acc[mt][nt][1] + b1;
            float v2 = acc[mt][nt][2] + b0, v3 = acc[mt][nt][3] + b1;
            if (ACT == 1) { v0 = tanhf(v0); v1 = tanhf(v1); v2 = tanhf(v2); v3 = tanhf(v3); }
            *(float2*)&dA[n] = make_float2(v0, v1);
            *(float2*)&dB[n] = make_float2(v2, v3);
        }
    }
}

// ============ HMMA diff-square GEMM, full-N tile, pipelined ============
template<int MODE>
__global__ void __launch_bounds__(256)
hmma_diffsq(const float* __restrict__ X, const float* __restrict__ Y,
            const float* __restrict__ rowinv,
            const __nv_bfloat16* __restrict__ Bh, const __nv_bfloat16* __restrict__ Bl,
            const float* __restrict__ bias, float* __restrict__ outp)
{
    extern __shared__ char smem[];
    uint32_t sb = smem_u32(smem);
    float* sred = (float*)(smem + DS_RED);
    float* sinv = (float*)(smem + DS_INV);
    int tid = threadIdx.x;
    int lane = tid & 31, warp = tid >> 5;
    int mw = warp >> 2, nw = warp & 3;
    int m0 = blockIdx.x * 128, z = blockIdx.y;

    const float* Xp = (MODE == 0) ? X + ((size_t)z*2304 + m0)*ND : X + (size_t)m0*ND;
    const float* Yp = (MODE == 0) ? Y + (size_t)m0*ND : Y + (size_t)z*ND;
    const float* invp = (MODE == 0) ? rowinv + (size_t)z*2304 + m0 : nullptr;

    float acc[4][8][4];
    #pragma unroll
    for (int i = 0; i < 4; i++)
        #pragma unroll
        for (int j = 0; j < 8; j++)
            #pragma unroll
            for (int e = 0; e < 4; e++) acc[i][j][e] = 0.f;

    int a_row = mw*64 + (lane & 15);
    int a_col8 = (lane >> 4) * 8;
    int b_row = nw*64 + (lane >> 4)*8 + (lane & 7);
    int b_col8 = ((lane >> 3) & 1) * 8;

    int arow[4], aq[4];
    float ivr[4];
    #pragma unroll
    for (int i = 0; i < 4; i++) {
        int slot = tid + i*256;
        arow[i] = slot >> 3; aq[i] = slot & 7;
        ivr[i] = (MODE == 0) ? invp[arow[i]] : 1.f;
    }

    float4 xr[4], yr[4];
    auto load_regs = [&](int ch) {
        int k0 = ch * 32;
        #pragma unroll
        for (int i = 0; i < 4; i++) {
            size_t off = (size_t)arow[i]*ND + k0 + aq[i]*4;
            xr[i] = *(const float4*)(Xp + off);
            if (MODE == 0) yr[i] = *(const float4*)(Yp + off);
            else           yr[i] = *(const float4*)(Yp + k0 + aq[i]*4);
        }
    };
    auto issueB = [&](int ch, int stage) {
        int k0 = ch * 32;
        uint32_t bh = sb + DS_BH + stage*20480;
        uint32_t bl = sb + DS_BL + stage*20480;
        #pragma unroll
        for (int i = 0; i < 4; i++) {
            int slot = tid + i*256;
            int row = slot >> 2, c = slot & 3;
            uint32_t so = (uint32_t)(row*APAD + c*8) * 2;
            size_t src = (size_t)row*ND + k0 + c*8;
            cp_async16(bh + so, Bh + src);
            cp_async16(bl + so, Bl + src);
        }
    };

    load_regs(0);
    issueB(0, 0); CP_COMMIT();

    for (int ch = 0; ch < 32; ch++) {
        int stage = ch & 1;
        #pragma unroll
        for (int i = 0; i < 4; i++) {
            float iv = ivr[i];
            float d0, d1, d2, d3;
            if (MODE == 0) {
                d0 = xr[i].x*iv - yr[i].x; d1 = xr[i].y*iv - yr[i].y;
                d2 = xr[i].z*iv - yr[i].z; d3 = xr[i].w*iv - yr[i].w;
            } else {
                d0 = xr[i].x - yr[i].x; d1 = xr[i].y - yr[i].y;
                d2 = xr[i].z - yr[i].z; d3 = xr[i].w - yr[i].w;
            }
            float a0 = d0*d0, a1 = d1*d1, a2 = d2*d2, a3 = d3*d3;
            __nv_bfloat162 h01 = __floats2bfloat162_rn(a0, a1);
            __nv_bfloat162 h23 = __floats2bfloat162_rn(a2, a3);
            float r0 = a0 - __bfloat162float(h01.x);
            float r1 = a1 - __bfloat162float(h01.y);
            float r2 = a2 - __bfloat162float(h23.x);
            float r3 = a3 - __bfloat162float(h23.y);
            __nv_bfloat162 l01 = __floats2bfloat162_rn(r0, r1);
            __nv_bfloat162 l23 = __floats2bfloat162_rn(r2, r3);
            uint32_t so = (uint32_t)(arow[i]*APAD + aq[i]*4) * 2;
            *(uint2*)(smem + DS_AH + so) = make_uint2(*(uint32_t*)&h01, *(uint32_t*)&h23);
            *(uint2*)(smem + DS_AL + so) = make_uint2(*(uint32_t*)&l01, *(uint32_t*)&l23);
        }
        if (ch < 31) {
            load_regs(ch + 1);
            issueB(ch + 1, stage ^ 1); CP_COMMIT();
            CP_WAIT1();
        } else {
            CP_WAIT0();
        }
        __syncthreads();
        uint32_t aAh = sb + DS_AH, aAl = sb + DS_AL;
        uint32_t aBh = sb + DS_BH + stage*20480;
        uint32_t aBl = sb + DS_BL + stage*20480;
        #pragma unroll
        for (int k16 = 0; k16 < 2; k16++) {
            uint32_t bh[8][2], bl[8][2];
            #pragma unroll
            for (int p = 0; p < 4; p++) {
                uint32_t off = (uint32_t)((b_row + p*16)*APAD + k16*16 + b_col8) * 2;
                uint32_t r0, r1, r2, r3;
                LDSM4(r0, r1, r2, r3, aBh + off);
                bh[p*2+0][0] = r0; bh[p*2+0][1] = r1;
                bh[p*2+1][0] = r2; bh[p*2+1][1] = r3;
                LDSM4(r0, r1, r2, r3, aBl + off);
                bl[p*2+0][0] = r0; bl[p*2+0][1] = r1;
                bl[p*2+1][0] = r2; bl[p*2+1][1] = r3;
            }
            #pragma unroll
            for (int mt = 0; mt < 4; mt++) {
                uint32_t ah[4], al[4];
                uint32_t off = (uint32_t)((a_row + mt*16)*APAD + k16*16 + a_col8) * 2;
                LDSM4(ah[0], ah[1], ah[2], ah[3], aAh + off);
                LDSM4(al[0], al[1], al[2], al[3], aAl + off);
                #pragma unroll
                for (int nt = 0; nt < 8; nt++) {
                    MMA_BF16(acc[mt][nt], ah, bh[nt]);
                    MMA_BF16(acc[mt][nt], ah, bl[nt]);
                    MMA_BF16(acc[mt][nt], al, bh[nt]);
                }
            }
        }
        __syncthreads();
    }

    #pragma unroll
    for (int mt = 0; mt < 4; mt++) {
        int lmA = mw*64 + mt*16 + (lane >> 2);
        int lmB = lmA + 8;
        int mA = m0 + lmA, mB = m0 + lmB;
        float vA[8][2], vB[8][2];
        float ssqA = 0.f, ssqB = 0.f;
        #pragma unroll
        for (int nt = 0; nt < 8; nt++) {
            int n = nw*64 + nt*8 + (lane & 3)*2;
            float b0 = bias[n], b1 = bias[n+1];
            vA[nt][0] = fmaxf(acc[mt][nt][0] + b0, 0.f);
            vA[nt][1] = fmaxf(acc[mt][nt][1] + b1, 0.f);
            vB[nt][0] = fmaxf(acc[mt][nt][2] + b0, 0.f);
            vB[nt][1] = fmaxf(acc[mt][nt][3] + b1, 0.f);
            if (MODE == 0) {
                ssqA += vA[nt][0]*vA[nt][0] + vA[nt][1]*vA[nt][1];
                ssqB += vB[nt][0]*vB[nt][0] + vB[nt][1]*vB[nt][1];
            }
        }
        float invA = 1.f, invB = 1.f;
        if (MODE == 0) {
            ssqA += __shfl_xor_sync(0xffffffffu, ssqA, 1);
            ssqA += __shfl_xor_sync(0xffffffffu, ssqA, 2);
            ssqB += __shfl_xor_sync(0xffffffffu, ssqB, 1);
            ssqB += __shfl_xor_sync(0xffffffffu, ssqB, 2);
            if ((lane & 3) == 0) {
                sred[nw*64 + mw*32 + (lane >> 2)] = ssqA;
                sred[nw*64 + mw*32 + 16 + (lane >> 2)] = ssqB;
            }
            __syncthreads();
            if (tid < 64) {
                float s = sred[0*64 + tid] + sred[1*64 + tid] + sred[2*64 + tid] + sred[3*64 + tid];
                sinv[tid] = 1.f / (sqrtf(s) + EPSL);
            }
            __syncthreads();
            invA = sinv[mw*32 + (lane >> 2)];
            invB = sinv[mw*32 + 16 + (lane >> 2)];
        }
        float* dA;
        float* dB;
        if (MODE == 0) {
            int bA = mA / NR, rA2 = mA % NR;
            int bB = mB / NR, rB2 = mB % NR;
            dA = outp + (((size_t)z*NB + bA)*37 + 1 + rA2)*NS;
            dB = outp + (((size_t)z*NB + bB)*37 + 1 + rB2)*NS;
        } else {
            dA = outp + ((size_t)z*2304 + mA)*NS;
            dB = outp + ((size_t)z*2304 + mB)*NS;
        }
        #pragma unroll
        for (int nt = 0; nt < 8; nt++) {
            int n = nw*64 + nt*8 + (lane & 3)*2;
            *(float2*)&dA[n] = make_float2(vA[nt][0]*invA, vA[nt][1]*invA);
            *(float2*)&dB[n] = make_float2(vB[nt][0]*invB, vB[nt][1]*invB);
        }
        if (MODE == 0) __syncthreads();
    }
}

// ============ small-M GEMM via split-K ============
__global__ void gemm_small_part(const float* __restrict__ A, const float* __restrict__ W,
                                float* __restrict__ part, int M, int N, int K)
{
    const int BK = 16;
    __shared__ float As[BK][64];
    __shared__ float Bs[BK][64];
    int tid = threadIdx.x, tr = tid >> 4, tc = tid & 15;
    int n0 = blockIdx.x * 64;
    int KS = gridDim.y;
    int Kc = K / KS;
    int kz = blockIdx.y;
    float acc[4][4] = {};
    for (int k0 = kz*Kc; k0 < (kz+1)*Kc; k0 += BK) {
        for (int i = tid; i < 64*BK; i += 256) {
            int m = i >> 4, k = i & 15;
            As[k][m] = (m < M) ? A[(size_t)m*K + k0 + k] : 0.f;
        }
        for (int i = tid; i < BK*64; i += 256) {
            int k = i >> 6, n = i & 63;
            Bs[k][n] = W[(size_t)(k0+k)*N + n0 + n];
        }
        __syncthreads();
        #pragma unroll
        for (int k = 0; k < BK; k++) {
            float a[4], b[4];
            #pragma unroll
            for (int i = 0; i < 4; i++) a[i] = As[k][tr*4+i];
            #pragma unroll
            for (int j = 0; j < 4; j++) b[j] = Bs[k][tc*4+j];
            #pragma unroll
            for (int i = 0; i < 4; i++)
                #pragma unroll
                for (int j = 0; j < 4; j++) acc[i][j] += a[i]*b[j];
        }
        __syncthreads();
    }
    #pragma unroll
    for (int i = 0; i < 4; i++) {
        int m = tr*4 + i;
        if (m >= M) continue;
        #pragma unroll
        for (int j = 0; j < 4; j++)
            part[((size_t)kz*M + m)*N + n0 + tc*4 + j] = acc[i][j];
    }
}

template<int ACT>
__global__ void k_small_epi(const float* __restrict__ part, const float* __restrict__ bias,
                            float* __restrict__ C, int M, int N, int KS)
{
    int idx = blockIdx.x*256 + threadIdx.x;
    if (idx >= M*N) return;
    int n = idx % N;
    float s = 0.f;
    for (int kz = 0; kz < KS; kz++) s += part[(size_t)kz*M*N + idx];
    s += bias[n];
    if (ACT == 1) s = tanhf(s);
    C[idx] = s;
}

// ---------------- tiny glo diff-square GEMM ----------------
__global__ void gemm_diffsq_glo(const float* __restrict__ X, const float* __restrict__ Y,
                                const float* __restrict__ W, const float* __restrict__ bias,
                                float* __restrict__ Cbase, int M, int N, int K)
{
    const int BM = 64, BN = 64, BK = 16;
    int c = blockIdx.z;
    const float* Yp = Y + (size_t)c*K;
    __shared__ float As[BK][BM];
    __shared__ float Bs[BK][BN];
    int tid = threadIdx.x;
    int tr = tid >> 4, tc = tid & 15;
    int m0 = blockIdx.y * BM, n0 = blockIdx.x * BN;
    float acc[4][4] = {};
    for (int k0 = 0; k0 < K; k0 += BK) {
        #pragma unroll
        for (int i = tid; i < BM*BK; i += 256) {
            int m = i >> 4, k = i & 15;
            float v = 0.f;
            if (m0 + m < M) {
                float d = X[(size_t)(m0+m)*K + k0 + k] - Yp[k0 + k];
                v = d * d;
            }
            As[k][m] = v;
        }
        #pragma unroll
        for (int i = tid; i < BK*BN; i += 256) {
            int k = i >> 6, n = i & 63;
            Bs[k][n] = W[(size_t)(k0+k)*N + n0 + n];
        }
        __syncthreads();
        #pragma unroll
        for (int k = 0; k < BK; k++) {
            float a[4], b[4];
            #pragma unroll
            for (int i = 0; i < 4; i++) a[i] = As[k][tr*4+i];
            #pragma unroll
            for (int j = 0; j < 4; j++) b[j] = Bs[k][tc*4+j];
            #pragma unroll
            for (int i = 0; i < 4; i++)
                #pragma unroll
                for (int j = 0; j < 4; j++) acc[i][j] += a[i]*b[j];
        }
        __syncthreads();
    }
    #pragma unroll
    for (int i = 0; i < 4; i++) {
        int m = m0 + tr*4 + i;
        if (m >= M) continue;
        #pragma unroll
        for (int j = 0; j < 4; j++) {
            int n = n0 + tc*4 + j;
            float v = fmaxf(acc[i][j] + bias[n], 0.f);
            Cbase[(size_t)c*M*N + (size_t)m*N + n] = v;
        }
    }
}

// ---------------- small kernels ----------------
__global__ void k_imgave(const float* __restrict__ img) {
    int i = blockIdx.x*blockDim.x + threadIdx.x;
    int b = i >> 10, d = i & 1023;
    float s = 0.f;
    for (int r = 0; r < NR; r++) s += img[((size_t)b*NR + r)*ND + d];
    g_imgave[i] = s * (1.f / NR);
}

__global__ void k_bnstats() {
    int r = blockIdx.x;
    __shared__ float red[256], red2[256];
    float s = 0.f, ss = 0.f;
    for (int i = threadIdx.x; i < NB*ND; i += 256) {
        int b = i >> 10, d = i & 1023;
        float v = g_h[((size_t)b*NR + r)*ND + d];
        s += v; ss += v*v;
    }
    red[threadIdx.x] = s; red2[threadIdx.x] = ss; __syncthreads();
    for (int st = 128; st > 0; st >>= 1) {
        if (threadIdx.x < st) { red[threadIdx.x] += red[threadIdx.x+st]; red2[threadIdx.x] += red2[threadIdx.x+st]; }
        __syncthreads();
    }
    if (threadIdx.x == 0) {
        float mu = red[0] / (float)(NB*ND);
        g_bnmu[r] = mu;
        g_bnvar[r] = red2[0] / (float)(NB*ND) - mu*mu;
    }
}

__global__ void k_gbn(const float* __restrict__ gamma, const float* __restrict__ beta) {
    int d = blockIdx.x*blockDim.x + threadIdx.x;
    float s = 0.f, ss = 0.f;
    for (int b = 0; b < NB; b++) { float v = g_g[(size_t)b*ND + d]; s += v; ss += v*v; }
    float mu = s / NB;
    float var = ss / NB - mu*mu;
    float inv = rsqrtf(var + BNEPS);
    float ga = gamma[d], be = beta[d];
    for (int b = 0; b < NB; b++) {
        float v = g_g[(size_t)b*ND + d];
        g_g[(size_t)b*ND + d] = tanhf((v - mu)*inv*ga + be);
    }
}

__global__ void k_wraw(const float* __restrict__ vcw, const float* __restrict__ vcb,
                       const float* __restrict__ lg, const float* __restrict__ lb) {
    int br = blockIdx.x;
    int b = br / NR, r = br % NR;
    __shared__ float red[256];
    float mu = g_bnmu[r], inv = rsqrtf(g_bnvar[r] + BNEPS);
    float ga = lg[r], be = lb[r];
    float s = 0.f;
    for (int d = threadIdx.x; d < ND; d += 256) {
        float le = tanhf((g_h[(size_t)br*ND + d] - mu)*inv*ga + be);
        s += le * g_g[(size_t)b*ND + d] * vcw[d];
    }
    float tot = blockReduceSum256(s, red);
    if (threadIdx.x == 0) g_wraw[br] = tot + vcb[0];
}

__global__ void k_newglobal(const float* __restrict__ img) {
    int b = blockIdx.x;
    __shared__ float w[NR];
    __shared__ float red[256];
    __shared__ float invn;
    if (threadIdx.x == 0) {
        float mx = -1e30f;
        for (int r = 0; r < NR; r++) mx = fmaxf(mx, g_wraw[b*NR + r]);
        float sum = 0.f;
        for (int r = 0; r < NR; r++) { w[r] = expf(g_wraw[b*NR + r] - mx); sum += w[r]; }
        float is = 1.f / sum;
        for (int r = 0; r < NR; r++) w[r] *= is;
    }
    __syncthreads();
    float ssq = 0.f;
    for (int d = threadIdx.x; d < ND; d += 256) {
        float s = 0.f;
        for (int r = 0; r < NR; r++) s += w[r] * img[((size_t)b*NR + r)*ND + d];
        g_imgglo[(size_t)b*ND + d] = s;
        ssq += s*s;
    }
    float tot = blockReduceSum256(ssq, red);
    if (threadIdx.x == 0) {
        float nrm = sqrtf(tot) + EPSL;
        g_normglo[b] = nrm;
        invn = 1.f / nrm;
    }
    __syncthreads();
    for (int d = threadIdx.x; d < ND; d += 256) g_imgglo[(size_t)b*ND + d] *= invn;
}

__global__ void k_imgpar(const float* __restrict__ img, const int* __restrict__ adjs) {
    int br = blockIdx.x;
    int b = br / NR, r = br % NR;
    __shared__ int eff[NPART];
    __shared__ float wg[NPART];
    if (threadIdx.x == 0) {
        int cnt = 0;
        const int* row = adjs + (size_t)b*NR*NR + (size_t)r*NR;
        for (int j = 0; j < NR && cnt < NPART; j++)
            if (row[j] == 1) eff[cnt++] = j;
        for (; cnt < NPART; cnt++) eff[cnt] = r;
        float v[NPART], mx = -1e30f;
        for (int k = 0; k < NPART; k++) { v[k] = g_wraw[b*NR + eff[k]]; mx = fmaxf(mx, v[k]); }
        float sum = 0.f;
        for (int k = 0; k < NPART; k++) { v[k] = expf(v[k] - mx); sum += v[k]; }
        float is = 1.f / sum;
        for (int k = 0; k < NPART; k++) wg[k] = v[k]*is;
    }
    __syncthreads();
    float invn = 1.f / g_normglo[b];
    for (int d = threadIdx.x; d < ND; d += 256) {
        float s = 0.f;
        #pragma unroll
        for (int k = 0; k < NPART; k++) s += wg[k] * img[((size_t)b*NR + eff[k])*ND + d];
        g_imgpar[(size_t)br*ND + d] = s * invn;
    }
}

__global__ void k_capave(const float* __restrict__ cap) {
    int i = blockIdx.x*blockDim.x + threadIdx.x;
    int c = i >> 10, d = i & 1023;
    float s = 0.f;
    for (int n = 0; n < NWD; n++) s += cap[((size_t)c*NWD + n)*ND + d];
    g_capave[i] = s * (1.f / NWD);
}

__global__ void k_capglo(const float* __restrict__ cap, const float* __restrict__ tsacw,
                         const float* __restrict__ tsacb) {
    int c = blockIdx.x;
    __shared__ float red[256];
    __shared__ float cw[NWD];
    __shared__ float invn;
    float gw[4];
    #pragma unroll
    for (int i = 0; i < 4; i++) {
        int d = threadIdx.x + i*256;
        gw[i] = g_ge[(size_t)c*ND + d] * tsacw[d];
    }
    for (int n = 0; n < NWD; n++) {
        float s = 0.f;
        #pragma unroll
        for (int i = 0; i < 4; i++) {
            int d = threadIdx.x + i*256;
            s += g_le[((size_t)c*NWD + n)*ND + d] * gw[i];
        }
        float tot = blockReduceSum256(s, red);
        if (threadIdx.x == 0) cw[n] = tot + tsacb[0];
    }
    __syncthreads();
    if (threadIdx.x == 0) {
        float mx = -1e30f;
        for (int n = 0; n < NWD; n++) mx = fmaxf(mx, cw[n]);
        float sum = 0.f;
        for (int n = 0; n < NWD; n++) { cw[n] = expf(cw[n] - mx); sum += cw[n]; }
        float is = 1.f / sum;
        for (int n = 0; n < NWD; n++) cw[n] *= is;
    }
    __syncthreads();
    float ssq = 0.f;
    #pragma unroll
    for (int i = 0; i < 4; i++) {
        int d = threadIdx.x + i*256;
        float s = 0.f;
        for (int n = 0; n < NWD; n++) s += cw[n] * cap[((size_t)c*NWD + n)*ND + d];
        g_capglo[(size_t)c*ND + d] = s;
        ssq += s*s;
    }
    float tot = blockReduceSum256(ssq, red);
    if (threadIdx.x == 0) invn = 1.f / (sqrtf(tot) + EPSL);
    __syncthreads();
    #pragma unroll
    for (int i = 0; i < 4; i++) {
        int d = threadIdx.x + i*256;
        g_capglo[(size_t)c*ND + d] *= invn;
    }
}

__global__ void k_attnfuse() {
    int cb = blockIdx.x;
    int c = cb / NB, b = cb % NB;
    __shared__ float sA[NWD*NR];
    __shared__ float nrm[NWD];
    const float* raw = g_attnraw + (size_t)c*NWD*NB*NR;
    for (int i = threadIdx.x; i < NWD*NR; i += 256) {
        int n = i / NR, r = i % NR;
        float v = raw[(size_t)n*NB*NR + (size_t)b*NR + r];
        v = (v > 0.f) ? v : 0.1f*v;
        sA[i] = v;
    }
    __syncthreads();
    if (threadIdx.x < NWD) {
        int n = threadIdx.x;
        float s = 0.f;
        for (int r = 0; r < NR; r++) { float v = sA[n*NR + r]; s += v*v; }
        nrm[n] = 1.f / (sqrtf(s) + EPSL);
    }
    __syncthreads();
    if (threadIdx.x < NR) {
        int r = threadIdx.x;
        float vals[NWD];
        float mx = -1e30f;
        for (int n = 0; n < NWD; n++) {
            float v = SMOOTHF * sA[n*NR + r] * nrm[n];
            vals[n] = v;
            mx = fmaxf(mx, v);
        }
        float sum = 0.f;
        for (int n = 0; n < NWD; n++) { vals[n] = expf(vals[n] - mx); sum += vals[n]; }
        float is = 1.f / sum;
        size_t base = ((size_t)cb*NR + r) * 64;
        for (int n = 0; n < 64; n++) {
            float w = (n < NWD) ? vals[n]*is : 0.f;
            __nv_bfloat16 h = __float2bfloat16(w);
            g_attnTh[base + n] = h;
            g_attnTl[base + n] = __float2bfloat16(w - __bfloat162float(h));
        }
    }
}

__global__ void k_ctxssq() {
    int row = blockIdx.x * 8 + (threadIdx.x >> 5);
    int lane = threadIdx.x & 31;
    const float* p = g_ctx + (size_t)row * ND;
    float s = 0.f;
    #pragma unroll
    for (int i = 0; i < 8; i++) {
        float4 v = *(const float4*)(p + lane*4 + i*128);
        s += v.x*v.x + v.y*v.y + v.z*v.z + v.w*v.w;
    }
    s = warpReduceSum(s);
    if (lane == 0) g_ctxinv[row] = 1.f / (sqrtf(s) + EPSL);
}

__global__ void k_rownorm(float* __restrict__ X, int L) {
    size_t row = blockIdx.x;
    float* p = X + row*(size_t)L;
    __shared__ float red[256];
    __shared__ float invn;
    float s = 0.f;
    for (int i = threadIdx.x; i < L; i += 256) { float v = p[i]; s += v*v; }
    float tot = blockReduceSum256(s, red);
    if (threadIdx.x == 0) invn = 1.f / (sqrtf(tot) + EPSL);
    __syncthreads();
    for (int i = threadIdx.x; i < L; i += 256) p[i] *= invn;
}

__global__ void k_finalize(const float* __restrict__ simw, const float* __restrict__ simb,
                           const float* __restrict__ lng, const float* __restrict__ lnb,
                           float* __restrict__ out, size_t out2off) {
    int cb = blockIdx.x;
    int tid = threadIdx.x;
    int lane = tid & 31, warp = tid >> 5;
    const float* sg = out + out2off + (size_t)cb*NS;
    __shared__ float sSgw[NS];
    __shared__ float wv[NR];
    __shared__ float mv[2];
    float sgv = sg[tid];
    sSgw[tid] = sgv * simw[tid];
    __syncthreads();
    const float* sp = g_simpar + (size_t)cb*NR*NS;
    for (int r = warp; r < NR; r += 8) {
        const float* row = sp + (size_t)r*NS;
        float dot = 0.f, ss = 0.f;
        #pragma unroll
        for (int i = 0; i < 8; i++) {
            int c = lane + i*32;
            float v = row[c];
            dot += v * sSgw[c];
            ss += v * v;
        }
        dot = warpReduceSum(dot);
        ss = warpReduceSum(ss);
        if (lane == 0) wv[r] = dot / (sqrtf(ss) + EPSL) + simb[0];
    }
    __syncthreads();
    if (tid == 0) {
        float m = 0.f;
        for (int r = 0; r < NR; r++) m += wv[r];
        m /= NR;
        float v = 0.f;
        for (int r = 0; r < NR; r++) { float d = wv[r] - m; v += d*d; }
        v /= NR;
        mv[0] = m; mv[1] = rsqrtf(v + LNEPS);
    }
    __syncthreads();
    if (tid < NR) {
        int r = tid;
        float z = (wv[r] - mv[0])*mv[1]*lng[r] + lnb[r];
        wv[r] = 1.f / (1.f + expf(-z));
    }
    __syncthreads();
    float* ob = out + (size_t)cb*37*NS;
    ob[tid] = sgv;
    for (int r = 0; r < NR; r++) ob[(size_t)(1+r)*NS + tid] *= wv[r];
}

// ---------------- host ----------------
extern "C" void kernel_launch(void* const* d_in, const int* in_sizes, int n_in,
                              void* d_out, int out_size) {
    (void)in_sizes; (void)n_in; (void)out_size;
    const float* img    = (const float*)d_in[0];
    const float* cap    = (const float*)d_in[1];
    const int*   adjs   = (const int*)d_in[3];
    const float* tsa_lw = (const float*)d_in[5];
    const float* tsa_lb = (const float*)d_in[6];
    const float* tsa_gw = (const float*)d_in[7];
    const float* tsa_gb = (const float*)d_in[8];
    const float* tsa_cw = (const float*)d_in[9];
    const float* tsa_cb = (const float*)d_in[10];
    const float* vl_w   = (const float*)d_in[11];
    const float* vl_b   = (const float*)d_in[12];
    const float* vbn_lg = (const float*)d_in[13];
    const float* vbn_lb = (const float*)d_in[14];
    const float* vg_w   = (const float*)d_in[15];
    const float* vg_b   = (const float*)d_in[16];
    const float* vbn_gg = (const float*)d_in[17];
    const float* vbn_gb = (const float*)d_in[18];
    const float* vc_w   = (const float*)d_in[19];
    const float* vc_b   = (const float*)d_in[20];
    const float* loc_w  = (const float*)d_in[21];
    const float* loc_b  = (const float*)d_in[22];
    const float* par_w  = (const float*)d_in[23];
    const float* par_b  = (const float*)d_in[24];
    const float* glo_w  = (const float*)d_in[25];
    const float* glo_b  = (const float*)d_in[26];
    const float* sim_w  = (const float*)d_in[27];
    const float* sim_b  = (const float*)d_in[28];
    const float* ln_g   = (const float*)d_in[29];
    const float* ln_b   = (const float*)d_in[30];
    float* out = (float*)d_out;

    static bool inited = false;
    static float *p_h, *p_imgave, *p_g, *p_ge, *p_le, *p_attnraw,
                 *p_ctx, *p_ctxinv, *p_imgpar, *p_imgglo, *p_capglo, *p_simpar, *p_part, *p_capave;
    static __nv_bfloat16 *p_wth, *p_wtl, *p_imgh, *p_imgl, *p_caph, *p_capl, *p_wbh, *p_wbl,
                         *p_attnTh, *p_attnTl, *p_capTh, *p_capTl;
    static cudaStream_t s1;
    static cudaEvent_t evFork, evJoin;
    if (!inited) {
        cudaGetSymbolAddress((void**)&p_h, g_h);
        cudaGetSymbolAddress((void**)&p_imgave, g_imgave);
        cudaGetSymbolAddress((void**)&p_g, g_g);
        cudaGetSymbolAddress((void**)&p_ge, g_ge);
        cudaGetSymbolAddress((void**)&p_le, g_le);
        cudaGetSymbolAddress((void**)&p_attnraw, g_attnraw);
        cudaGetSymbolAddress((void**)&p_ctx, g_ctx);
        cudaGetSymbolAddress((void**)&p_ctxinv, g_ctxinv);
        cudaGetSymbolAddress((void**)&p_imgpar, g_imgpar);
        cudaGetSymbolAddress((void**)&p_imgglo, g_imgglo);
        cudaGetSymbolAddress((void**)&p_capglo, g_capglo);
        cudaGetSymbolAddress((void**)&p_simpar, g_simpar);
        cudaGetSymbolAddress((void**)&p_part, g_part);
        cudaGetSymbolAddress((void**)&p_capave, g_capave);
        cudaGetSymbolAddress((void**)&p_wth, g_wth);
        cudaGetSymbolAddress((void**)&p_wtl, g_wtl);
        cudaGetSymbolAddress((void**)&p_imgh, g_imgh);
        cudaGetSymbolAddress((void**)&p_imgl, g_imgl);
        cudaGetSymbolAddress((void**)&p_caph, g_caph);
        cudaGetSymbolAddress((void**)&p_capl, g_capl);
        cudaGetSymbolAddress((void**)&p_wbh, g_wbh);
        cudaGetSymbolAddress((void**)&p_wbl, g_wbl);
        cudaGetSymbolAddress((void**)&p_attnTh, g_attnTh);
        cudaGetSymbolAddress((void**)&p_attnTl, g_attnTl);
        cudaGetSymbolAddress((void**)&p_capTh, g_capTh);
        cudaGetSymbolAddress((void**)&p_capTl, g_capTl);
        cudaFuncSetAttribute(hmma_gemm<0>, cudaFuncAttributeMaxDynamicSharedMemorySize, GS_TOTAL);
        cudaFuncSetAttribute(hmma_gemm<1>, cudaFuncAttributeMaxDynamicSharedMemorySize, GS_TOTAL);
        cudaFuncSetAttribute(hmma_diffsq<0>, cudaFuncAttributeMaxDynamicSharedMemorySize, DS_TOTAL);
        cudaFuncSetAttribute(hmma_diffsq<1>, cudaFuncAttributeMaxDynamicSharedMemorySize, DS_TOTAL);
        cudaStreamCreateWithFlags(&s1, cudaStreamNonBlocking);
        cudaEventCreateWithFlags(&evFork, cudaEventDisableTiming);
        cudaEventCreateWithFlags(&evJoin, cudaEventDisableTiming);
        inited = true;
    }

    const size_t out2off = (size_t)NCAP*NB*37*NS;
    float* out2 = out + out2off;

    // ---- early launches (R12 order) ----
    k_split<<<(NB*NR*ND+255)/256, 256>>>(img, p_imgh, p_imgl, NB*NR*ND);
    k_wsplitT<<<(ND*ND+255)/256, 256>>>(vl_w, p_wbh, p_wbl, ND, ND);
    k_split<<<(NCAP*NWD*ND+255)/256, 256>>>(cap, p_caph, p_capl, NCAP*NWD*ND);
    k_wsplitT<<<(ND*ND+255)/256, 256>>>(tsa_lw, p_wbh + ND*ND, p_wbl + ND*ND, ND, ND);
    k_imgave<<<256, 256>>>(img);
    hmma_gemm<0><<<dim3(8, 18), 256, GS_TOTAL>>>(p_imgh, p_imgl, p_wbh, p_wbl,
                                                 vl_b, p_h, ND, ND, 0, 0, 0);
    k_wsplitT<<<(NS*ND+255)/256, 256>>>(loc_w, p_wth,         p_wtl,         NS, ND);
    k_wsplitT<<<(NS*ND+255)/256, 256>>>(par_w, p_wth + NS*ND, p_wtl + NS*ND, NS, ND);
    k_capT<<<(NCAP*ND*64+255)/256, 256>>>(cap);

    // ---- caption-independent ----
    k_bnstats<<<NR, 256>>>();
    gemm_small_part<<<dim3(16, 8), 256>>>(p_imgave, vg_w, p_part, NB, ND, ND);
    k_small_epi<0><<<(NB*ND+255)/256, 256>>>(p_part, vg_b, p_g, NB, ND, 8);
    k_gbn<<<4, 256>>>(vbn_gg, vbn_gb);
    k_wraw<<<NB*NR, 256>>>(vc_w, vc_b, vbn_lg, vbn_lb);
    k_newglobal<<<NB, 256>>>(img);
    k_imgpar<<<NB*NR, 256>>>(img, adjs);

    // ---- caption side ----
    k_capave<<<128, 256>>>(cap);
    hmma_gemm<1><<<dim3(8, 10), 256, GS_TOTAL>>>(p_caph, p_capl, p_wbh + ND*ND, p_wbl + ND*ND,
                                                 tsa_lb, p_le, ND, ND, 0, 0, 0);
    gemm_small_part<<<dim3(16, 8), 256>>>(p_capave, tsa_gw, p_part, NCAP, ND, ND);
    k_small_epi<1><<<(NCAP*ND+255)/256, 256>>>(p_part, tsa_gb, p_ge, NCAP, ND, 8);
    k_capglo<<<NCAP, 256>>>(cap, tsa_cw, tsa_cb);

    // ---- fork: independent branch on s1 (simpar + sim_glo) ----
    cudaEventRecord(evFork, 0);
    cudaStreamWaitEvent(s1, evFork, 0);
    hmma_diffsq<1><<<dim3(18, NCAP), 256, DS_TOTAL, s1>>>(p_imgpar, p_capglo, nullptr,
                                                          p_wth + NS*ND, p_wtl + NS*ND, par_b, p_simpar);
    gemm_diffsq_glo<<<dim3(4, 1, NCAP), 256, 0, s1>>>(p_imgglo, p_capglo, glo_w, glo_b, out2, NB, NS, ND);
    k_rownorm<<<NCAP*NB, 256, 0, s1>>>(out2, NS);
    cudaEventRecord(evJoin, s1);

    // ---- main branch: attn -> ctx -> diffsq0 ----
    hmma_gemm<0><<<dim3(18, 10), 256, GS_TOTAL>>>(p_caph, p_capl, p_imgh, p_imgl,
                                                  nullptr, p_attnraw, NB*NR, ND, 0, 0, 0);
    k_attnfuse<<<NCAP*NB, 256>>>();
    hmma_gemm<0><<<dim3(8, 18, NCAP), 256, GS_TOTAL>>>(p_attnTh, p_attnTl, p_capTh, p_capTl,
                                                       nullptr, p_ctx, ND, 64,
                                                       (size_t)2304*64, (size_t)ND*64, (size_t)2304*ND);
    k_ctxssq<<<NCAP*NB*NR/8, 256>>>();
    hmma_diffsq<0><<<dim3(18, NCAP), 256, DS_TOTAL>>>(p_ctx, img, p_ctxinv, p_wth, p_wtl, loc_b, out);

    // ---- join + finalize ----
    cudaStreamWaitEvent(0, evJoin, 0);
    k_finalize<<<NCAP*NB, 256>>>(sim_w, sim_b, ln_g, ln_b, out, out2off);
}